// round 12
// baseline (speedup 1.0000x reference)
#include <cuda_runtime.h>
#include <cstdint>

#define B_   256
#define D_   784
#define H_   1024
#define T_   10
#define NCH  18
#define CHLEN 44

#define KNEG (-1.4426950408889634f)   // -log2(e)

typedef unsigned long long ull;

// ---------------- scratch ----------------
__device__ __align__(16) float  g_Wt[D_ * H_];          // (-log2e)*W^T [D][H] (scalar, for chunksum)
__device__ __align__(16) float2 g_Wt2[D_ * H_];         // duplicated (w,w) pairs for k_main
__device__ __align__(16) float  g_Apre[NCH * B_ * H_];  // scaled chunk-start accumulators
__device__ __align__(16) float  g_logit[D_ * B_ * T_];  // atomic-accumulated logits [d][b][t]

// ---------------- helpers ----------------
__device__ __forceinline__ float ex2f(float x) {
    float y; asm("ex2.approx.f32 %0, %1;" : "=f"(y) : "f"(x)); return y;
}
__device__ __forceinline__ float rcpf(float x) {
    float y; asm("rcp.approx.f32 %0, %1;" : "=f"(y) : "f"(x)); return y;
}
__device__ __forceinline__ ull fma2_(ull a, ull b, ull c) {
    ull d; asm("fma.rn.f32x2 %0, %1, %2, %3;" : "=l"(d) : "l"(a), "l"(b), "l"(c)); return d;
}
__device__ __forceinline__ ull pack2_(float lo, float hi) {
    ull d; asm("mov.b64 %0, {%1, %2};" : "=l"(d) : "f"(lo), "f"(hi)); return d;
}
__device__ __forceinline__ void unpack2_(ull v, float& lo, float& hi) {
    asm("mov.b64 {%0, %1}, %2;" : "=f"(lo), "=f"(hi) : "l"(v));
}
__device__ __forceinline__ void cp_async16(float* s, const float* g) {
    unsigned sa = (unsigned)__cvta_generic_to_shared(s);
    asm volatile("cp.async.ca.shared.global [%0], [%1], 16;\n" :: "r"(sa), "l"(g));
}
__device__ __forceinline__ void cp_commit() {
    asm volatile("cp.async.commit_group;\n" ::: "memory");
}
// vector f32 atomic add, no return (sm_90+)
__device__ __forceinline__ void redg2(float* p, float lo, float hi) {
    asm volatile("red.global.add.v2.f32 [%0], {%1, %2};" :: "l"(p), "f"(lo), "f"(hi) : "memory");
}

// ---------------- K1: transpose W; write scalar + duplicated forms ----------------
__global__ void k_transW(const float* __restrict__ W) {
    __shared__ float tile[32][33];
    int d = blockIdx.x * 32 + threadIdx.x;
    int h = blockIdx.y * 32 + threadIdx.y;
#pragma unroll
    for (int j = 0; j < 32; j += 8)
        if (d < D_) tile[threadIdx.y + j][threadIdx.x] = W[(h + j) * D_ + d] * KNEG;
    __syncthreads();
    int ho = blockIdx.y * 32 + threadIdx.x;
    int do_ = blockIdx.x * 32 + threadIdx.y;
#pragma unroll
    for (int j = 0; j < 32; j += 8)
        if (do_ + j < D_) {
            float v = tile[threadIdx.x][threadIdx.y + j];
            g_Wt [(do_ + j) * H_ + ho] = v;
            g_Wt2[(do_ + j) * H_ + ho] = make_float2(v, v);
        }
}

// ---------------- K2: chunk sums ----------------
__global__ __launch_bounds__(512) void k_chunksum(const int* __restrict__ x) {
    int bg = blockIdx.x;        // 0..31 (8 batches each)
    int k  = blockIdx.y;
    int i0 = k * CHLEN;
    int len = min(CHLEN, D_ - i0);
    __shared__ float xs2[CHLEN * 8];
    int tid = threadIdx.x;
    for (int idx = tid; idx < len * 8; idx += 512) {
        int j = idx >> 3, b = idx & 7;
        xs2[idx] = (float)x[(size_t)(bg * 8 + b) * D_ + i0 + j];
    }
    __syncthreads();
    int h0 = blockIdx.z * 512 + tid;
    float acc[8];
#pragma unroll
    for (int b = 0; b < 8; b++) acc[b] = 0.f;
    float wn1 = g_Wt[i0 * H_ + h0];
    float wn2 = (len > 1) ? g_Wt[(i0 + 1) * H_ + h0] : 0.f;
    for (int j = 0; j < len; j++) {
        float wv = wn1;
        wn1 = wn2;
        if (j + 2 < len) wn2 = g_Wt[(i0 + j + 2) * H_ + h0];
        const float* xr = &xs2[j * 8];
#pragma unroll
        for (int b = 0; b < 8; b++)
            acc[b] = fmaf(xr[b], wv, acc[b]);
    }
#pragma unroll
    for (int b = 0; b < 8; b++)
        g_Apre[(size_t)(k * B_ + bg * 8 + b) * H_ + h0] = acc[b];
}

// ---------------- K3: exclusive prefix (MLP=18) + zero g_logit ----------------
__global__ void k_prefix(const float* __restrict__ c) {
    int idx = blockIdx.x * 256 + threadIdx.x;   // 131072 threads
    int b  = idx >> 9;
    int h0 = (idx & 511) * 2;
    float2 v[NCH];
#pragma unroll
    for (int k = 0; k < NCH; k++)
        v[k] = *(const float2*)&g_Apre[(size_t)(k * B_ + b) * H_ + h0];
    float2 acc = *(const float2*)&c[h0];
    acc.x *= KNEG; acc.y *= KNEG;
#pragma unroll
    for (int k = 0; k < NCH; k++) {
        *(float2*)&g_Apre[(size_t)(k * B_ + b) * H_ + h0] = acc;
        acc.x += v[k].x; acc.y += v[k].y;
    }
    // zero the logit accumulator (501760 float4's over 131072 threads)
    for (int q = idx; q < (D_ * B_ * T_) / 4; q += 131072)
        ((float4*)g_logit)[q] = make_float4(0.f, 0.f, 0.f, 0.f);
}

// ---------------- K4: main kernel — warp-autonomous, no block barriers ----------------
// per-warp smem: 3 V slots (320 f) + 3 W slots (64 f as 32 float2) = 1152 floats
#define WARP_SM 1152
#define SM_FLOATS (8 * WARP_SM)     // 9216 floats = 36864 B per block

__device__ __forceinline__ void stage_w(float* vslot, float* wslot, int i, int h0, int L,
                                        const float* __restrict__ V) {
    const float* vg = V + (size_t)i * (T_ * H_) + (size_t)h0 * T_;   // 320 floats, 16B-aligned
    cp_async16(vslot + L * 4,       vg + L * 4);
    cp_async16(vslot + 128 + L * 4, vg + 128 + L * 4);
    if (L < 16)
        cp_async16(vslot + 256 + L * 4, vg + 256 + L * 4);
    else
        cp_async16(wslot + (L - 16) * 4,
                   ((const float*)(g_Wt2 + (size_t)i * H_ + h0)) + (L - 16) * 4);
    cp_commit();
}

__global__ __launch_bounds__(256, 2) void k_main(const int* __restrict__ xi,
                                                 const float* __restrict__ V) {
    extern __shared__ float sm[];
    const int tid   = threadIdx.x;
    const int w     = tid >> 5;       // 0..7
    const int L     = tid & 31;
    const int tile  = blockIdx.x;     // 0..3  (64 batches)
    const int chunk = blockIdx.y;     // 0..NCH-1
    const int qh    = blockIdx.z;     // 0..3  (256 h)
    const int i0  = chunk * CHLEN;
    const int len = min(CHLEN, D_ - i0);
    const int h0  = qh * 256 + w * 32;   // this warp's 32 global h

    float* vbase = sm + w * WARP_SM;     // 3 x 320
    float* wbase = vbase + 3 * 320;      // 3 x 64

    // a2[u] = (A[b0][h0+u], A[b1][h0+u]); b0 = tile*64+L, b1 = b0+32
    ull a2[32];
    {
        const float* ap0 = g_Apre + ((size_t)(chunk * B_ + tile * 64 + L)) * H_ + h0;
        const float* ap1 = ap0 + (size_t)32 * H_;
#pragma unroll
        for (int g = 0; g < 8; g++) {
            float4 va = *(const float4*)(ap0 + 4 * g);
            float4 vb = *(const float4*)(ap1 + 4 * g);
            a2[4 * g + 0] = pack2_(va.x, vb.x);
            a2[4 * g + 1] = pack2_(va.y, vb.y);
            a2[4 * g + 2] = pack2_(va.z, vb.z);
            a2[4 * g + 3] = pack2_(va.w, vb.w);
        }
    }

    stage_w(vbase + 0,   wbase + 0,  i0,     h0, L, V);
    if (len > 1) stage_w(vbase + 320, wbase + 64, i0 + 1, h0, L, V);

    const int* xrow0 = xi + (size_t)(tile * 64 + L) * D_ + i0;
    const int* xrow1 = xrow0 + (size_t)32 * D_;
    float x0buf[2], x1buf[2];
    x0buf[0] = (float)__ldg(xrow0);     x1buf[0] = (float)__ldg(xrow1);
    x0buf[1] = (len > 1) ? (float)__ldg(xrow0 + 1) : 0.f;
    x1buf[1] = (len > 1) ? (float)__ldg(xrow1 + 1) : 0.f;

    int cur = 0, stg = 2;
    for (int s = 0; s < len; s++) {
        if (s + 1 < len) asm volatile("cp.async.wait_group 1;\n" ::: "memory");
        else             asm volatile("cp.async.wait_group 0;\n" ::: "memory");
        __syncwarp();    // all lanes waited own groups -> whole slot visible

        const ull x2 = pack2_(x0buf[s & 1], x1buf[s & 1]);
        if (s + 2 < len) {
            x0buf[s & 1] = (float)__ldg(xrow0 + s + 2);
            x1buf[s & 1] = (float)__ldg(xrow1 + s + 2);
            stage_w(vbase + stg * 320, wbase + stg * 64, i0 + s + 2, h0, L, V);
        }

        // ---- compute step s ----
        const float* Vp = vbase + cur * 320;
        const ull*   Wq = (const ull*)(wbase + cur * 64);

        ull accA[5], accB[5];
#pragma unroll
        for (int j = 0; j < 5; j++) { accA[j] = 0ull; accB[j] = 0ull; }

        float sb0, sb1;
        {
            float f0, f1;
            unpack2_(a2[0], f0, f1);
            sb0 = rcpf(1.f + ex2f(f0));
            sb1 = rcpf(1.f + ex2f(f1));
        }

#pragma unroll
        for (int u = 0; u < 32; u++) {
            float nb0 = 0.f, nb1 = 0.f;
            if (u < 31) {
                float f0, f1;
                unpack2_(a2[u + 1], f0, f1);
                nb0 = rcpf(1.f + ex2f(f0));
                nb1 = rcpf(1.f + ex2f(f1));
            }
            a2[u] = fma2_(x2, Wq[u], a2[u]);   // duplicated (w,w) straight from smem

            const float* vr = Vp + u * T_;     // 40B rows, 8B aligned
            const ull s0 = pack2_(sb0, sb0);
            const ull s1 = pack2_(sb1, sb1);
#pragma unroll
            for (int j = 0; j < 5; j++) {
                const ull vv = *(const ull*)(vr + 2 * j);
                accA[j] = fma2_(s0, vv, accA[j]);
                accB[j] = fma2_(s1, vv, accB[j]);
            }
            sb0 = nb0; sb1 = nb1;
        }

        // ---- atomically accumulate partial logits for step s ----
        {
            float* gl0 = g_logit + ((size_t)(i0 + s) * B_ + tile * 64 + L) * T_;
            float* gl1 = gl0 + 32 * T_;
#pragma unroll
            for (int j = 0; j < 5; j++) {
                float lo, hi;
                unpack2_(accA[j], lo, hi);
                redg2(gl0 + 2 * j, lo, hi);
                unpack2_(accB[j], lo, hi);
                redg2(gl1 + 2 * j, lo, hi);
            }
        }

        cur = (cur == 2) ? 0 : cur + 1;
        stg = (stg == 2) ? 0 : stg + 1;
    }
}

// ---------------- K5: bias + softmax + scatter ----------------
__global__ __launch_bounds__(256) void k_softmax(const float* __restrict__ bias,
                                                 float* __restrict__ out) {
    const int d = blockIdx.x;       // 0..783
    const int b = threadIdx.x;      // 0..255
    const float* lp = g_logit + ((size_t)d * B_ + b) * T_;
    float l[T_];
#pragma unroll
    for (int t = 0; t < T_; t++) l[t] = lp[t] + __ldg(bias + d * T_ + t);
    float mx = l[0];
#pragma unroll
    for (int t = 1; t < T_; t++) mx = fmaxf(mx, l[t]);
    float e[T_]; float sum = 0.f;
#pragma unroll
    for (int t = 0; t < T_; t++) {
        e[t] = ex2f((l[t] - mx) * 1.4426950408889634f);
        sum += e[t];
    }
    const float r = rcpf(sum);
    float* op = out + (size_t)b * (T_ * D_) + d;
#pragma unroll
    for (int t = 0; t < T_; t++) op[t * D_] = e[t] * r;
}

// ---------------- launch ----------------
extern "C" void kernel_launch(void* const* d_in, const int* in_sizes, int n_in,
                              void* d_out, int out_size) {
    const int*   x    = (const int*)d_in[0];
    const float* W    = (const float*)d_in[1];
    const float* c    = (const float*)d_in[2];
    const float* V    = (const float*)d_in[3];
    const float* bias = (const float*)d_in[4];
    float* out = (float*)d_out;

    static_assert(2 * SM_FLOATS * 4 <= 232448, "smem budget");
    cudaFuncSetAttribute(k_main, cudaFuncAttributeMaxDynamicSharedMemorySize,
                         SM_FLOATS * (int)sizeof(float));

    k_transW<<<dim3((D_ + 31) / 32, H_ / 32), dim3(32, 8)>>>(W);     // launch 1
    k_chunksum<<<dim3(32, NCH, 2), 512>>>(x);                        // launch 2
    k_prefix<<<(B_ * H_ / 2) / 256, 256>>>(c);                       // launch 3 (+ zero g_logit)
    k_main<<<dim3(4, NCH, 4), 256, SM_FLOATS * (int)sizeof(float)>>>(x, V);  // launch 4 -> profiled
    k_softmax<<<D_, 256>>>(bias, out);                               // launch 5
}

// round 13
// speedup vs baseline: 1.0849x; 1.0849x over previous
#include <cuda_runtime.h>
#include <cstdint>

#define B_   256
#define D_   784
#define H_   1024
#define T_   10
#define NCH  18
#define CHLEN 44

#define KNEG (-1.4426950408889634f)   // -log2(e)

typedef unsigned long long ull;

// ---------------- scratch ----------------
__device__ __align__(16) float  g_Wt[D_ * H_];          // (-log2e)*W^T [D][H] scalar
__device__ __align__(16) float2 g_Wt2[D_ * H_];         // duplicated (w,w)
__device__ __align__(16) float  g_xf[B_ * D_];          // x as float, same layout
__device__ __align__(16) float  g_Apre[NCH * B_ * H_];  // scaled chunk-start accumulators
__device__ __align__(16) ull    g_part[(size_t)D_ * 2 * 8 * 640]; // [d][tile2][qh8][j5*128c]

// ---------------- helpers ----------------
__device__ __forceinline__ float ex2f(float x) {
    float y; asm("ex2.approx.f32 %0, %1;" : "=f"(y) : "f"(x)); return y;
}
__device__ __forceinline__ float rcpf(float x) {
    float y; asm("rcp.approx.f32 %0, %1;" : "=f"(y) : "f"(x)); return y;
}
__device__ __forceinline__ ull fma2_(ull a, ull b, ull c) {
    ull d; asm("fma.rn.f32x2 %0, %1, %2, %3;" : "=l"(d) : "l"(a), "l"(b), "l"(c)); return d;
}
__device__ __forceinline__ ull add2_(ull a, ull b) {
    ull d; asm("add.rn.f32x2 %0, %1, %2;" : "=l"(d) : "l"(a), "l"(b)); return d;
}
__device__ __forceinline__ ull pack2_(float lo, float hi) {
    ull d; asm("mov.b64 %0, {%1, %2};" : "=l"(d) : "f"(lo), "f"(hi)); return d;
}
__device__ __forceinline__ void unpack2_(ull v, float& lo, float& hi) {
    asm("mov.b64 {%0, %1}, %2;" : "=f"(lo), "=f"(hi) : "l"(v));
}
__device__ __forceinline__ void cp_async16(float* s, const float* g) {
    unsigned sa = (unsigned)__cvta_generic_to_shared(s);
    asm volatile("cp.async.ca.shared.global [%0], [%1], 16;\n" :: "r"(sa), "l"(g));
}
__device__ __forceinline__ void cp_commit() {
    asm volatile("cp.async.commit_group;\n" ::: "memory");
}

// ---------------- K1: transpose W -> scalar + duplicated ----------------
__global__ void k_transW(const float* __restrict__ W) {
    __shared__ float tile[32][33];
    int d = blockIdx.x * 32 + threadIdx.x;
    int h = blockIdx.y * 32 + threadIdx.y;
#pragma unroll
    for (int j = 0; j < 32; j += 8)
        if (d < D_) tile[threadIdx.y + j][threadIdx.x] = W[(h + j) * D_ + d] * KNEG;
    __syncthreads();
    int ho = blockIdx.y * 32 + threadIdx.x;
    int do_ = blockIdx.x * 32 + threadIdx.y;
#pragma unroll
    for (int j = 0; j < 32; j += 8)
        if (do_ + j < D_) {
            float v = tile[threadIdx.x][threadIdx.y + j];
            g_Wt [(do_ + j) * H_ + ho] = v;
            g_Wt2[(do_ + j) * H_ + ho] = make_float2(v, v);
        }
}

// ---------------- K2: chunk sums ----------------
__global__ __launch_bounds__(512) void k_chunksum(const int* __restrict__ x) {
    int bg = blockIdx.x;
    int k  = blockIdx.y;
    int i0 = k * CHLEN;
    int len = min(CHLEN, D_ - i0);
    __shared__ float xs2[CHLEN * 8];
    int tid = threadIdx.x;
    for (int idx = tid; idx < len * 8; idx += 512) {
        int j = idx >> 3, b = idx & 7;
        xs2[idx] = (float)x[(size_t)(bg * 8 + b) * D_ + i0 + j];
    }
    __syncthreads();
    int h0 = blockIdx.z * 512 + tid;
    float acc[8];
#pragma unroll
    for (int b = 0; b < 8; b++) acc[b] = 0.f;
    float wn1 = g_Wt[i0 * H_ + h0];
    float wn2 = (len > 1) ? g_Wt[(i0 + 1) * H_ + h0] : 0.f;
    for (int j = 0; j < len; j++) {
        float wv = wn1;
        wn1 = wn2;
        if (j + 2 < len) wn2 = g_Wt[(i0 + j + 2) * H_ + h0];
        const float* xr = &xs2[j * 8];
#pragma unroll
        for (int b = 0; b < 8; b++)
            acc[b] = fmaf(xr[b], wv, acc[b]);
    }
#pragma unroll
    for (int b = 0; b < 8; b++)
        g_Apre[(size_t)(k * B_ + bg * 8 + b) * H_ + h0] = acc[b];
}

// ---------------- K3: exclusive prefix (MLP=18) + x float convert ----------------
__global__ void k_prefix(const float* __restrict__ c, const int* __restrict__ x) {
    int idx = blockIdx.x * 256 + threadIdx.x;   // 131072 threads
    int b  = idx >> 9;
    int h0 = (idx & 511) * 2;
    float2 v[NCH];
#pragma unroll
    for (int k = 0; k < NCH; k++)
        v[k] = *(const float2*)&g_Apre[(size_t)(k * B_ + b) * H_ + h0];
    float2 acc = *(const float2*)&c[h0];
    acc.x *= KNEG; acc.y *= KNEG;
#pragma unroll
    for (int k = 0; k < NCH; k++) {
        *(float2*)&g_Apre[(size_t)(k * B_ + b) * H_ + h0] = acc;
        acc.x += v[k].x; acc.y += v[k].y;
    }
    for (int q = idx; q < B_ * D_; q += 131072)
        g_xf[q] = (float)x[q];
}

// ---------------- K4: main (128 batches x 128 h per block; 4 batches/lane) ----------------
// smem (floats): V 3*1280 = 3840 ; Wdup 3*256 = 768 ; RED 2*10240 = 20480
#define SM_V   0
#define SM_W   3840
#define SM_RED 4608
#define SM_FLOATS 25088     // 100352 B/block; x2 = 200704 <= 232448

__device__ __forceinline__ void stage(float* sm, int i, int srel, int hbase, int tid,
                                      const float* __restrict__ V) {
    const int bb = srel % 3;
    const float* vg = V + (size_t)i * (T_ * H_) + (size_t)hbase * T_;   // 1280 floats
    float* vs = sm + SM_V + bb * 1280;
    cp_async16(vs + tid * 4, vg + tid * 4);                 // 1024 f
    if (tid < 64) cp_async16(vs + (256 + tid) * 4, vg + (256 + tid) * 4);  // 256 f
    else if (tid < 128)
        cp_async16(sm + SM_W + bb * 256 + (tid - 64) * 4,
                   ((const float*)(g_Wt2 + (size_t)i * H_ + hbase)) + (tid - 64) * 4);
}

__global__ __launch_bounds__(256, 2) void k_main(const float* __restrict__ V) {
    extern __shared__ float sm[];
    const int tid   = threadIdx.x;
    const int w     = tid >> 5;       // 0..7
    const int L     = tid & 31;
    const int tile  = blockIdx.x;     // 0..1  (128 batches)
    const int chunk = blockIdx.y;     // 0..NCH-1
    const int qh    = blockIdx.z;     // 0..7  (128 h)
    const int i0  = chunk * CHLEN;
    const int len = min(CHLEN, D_ - i0);
    const int hbase = qh * 128;
    const int hl  = w * 16;           // warp's local h
    const int h0  = hbase + hl;

    // a2[2u]=(A[b0][h0+u],A[b1][..]), a2[2u+1]=(A[b2],A[b3]); b_k = tile*128 + L + 32k
    ull a2[32];
    {
        const float* ap = g_Apre + ((size_t)(chunk * B_ + tile * 128 + L)) * H_ + h0;
#pragma unroll
        for (int g = 0; g < 4; g++) {
            float4 v0 = *(const float4*)(ap + 4 * g);
            float4 v1 = *(const float4*)(ap + (size_t)32 * H_ + 4 * g);
            float4 v2 = *(const float4*)(ap + (size_t)64 * H_ + 4 * g);
            float4 v3 = *(const float4*)(ap + (size_t)96 * H_ + 4 * g);
            const float* f0 = (const float*)&v0;
            const float* f1 = (const float*)&v1;
            const float* f2 = (const float*)&v2;
            const float* f3 = (const float*)&v3;
#pragma unroll
            for (int q = 0; q < 4; q++) {
                a2[2 * (4 * g + q)]     = pack2_(f0[q], f1[q]);
                a2[2 * (4 * g + q) + 1] = pack2_(f2[q], f3[q]);
            }
        }
    }

    stage(sm, i0, 0, hbase, tid, V); cp_commit();
    if (len > 1) { stage(sm, i0 + 1, 1, hbase, tid, V); cp_commit(); }

    const float* xr0 = g_xf + (size_t)(tile * 128 + L) * D_ + i0;

    for (int s = 0; s < len; s++) {
        if (s + 1 < len) asm volatile("cp.async.wait_group 1;\n" ::: "memory");
        else             asm volatile("cp.async.wait_group 0;\n" ::: "memory");
        __syncthreads();

        if (s + 2 < len) { stage(sm, i0 + s + 2, s + 2, hbase, tid, V); cp_commit(); }

        // deferred reduce of step s-1 by rotating warp
        if (s >= 1 && w == ((s - 1) & 7)) {
            const float* red = sm + SM_RED + ((s - 1) & 1) * 10240;
            ull* gp = g_part + (((size_t)(i0 + s - 1) * 2 + tile) * 8 + qh) * 640;
#pragma unroll
            for (int j = 0; j < 5; j++)
#pragma unroll
                for (int p = 0; p < 4; p++) {
                    const int c = p * 32 + L;
                    ull v = *(const ull*)(red + (0 * 640 + j * 128 + c) * 2);
#pragma unroll
                    for (int ww = 1; ww < 8; ww++)
                        v = add2_(v, *(const ull*)(red + (ww * 640 + j * 128 + c) * 2));
                    gp[j * 128 + c] = v;
                }
        }

        // ---- compute step s ----
        const float* Vp = sm + SM_V + (s % 3) * 1280;
        const ull*   Wq = (const ull*)(sm + SM_W + (s % 3) * 256);
        const ull xP = pack2_(xr0[s], xr0[(size_t)32 * D_ + s]);
        const ull xQ = pack2_(xr0[(size_t)64 * D_ + s], xr0[(size_t)96 * D_ + s]);

        ull acc[4][5];
#pragma unroll
        for (int k = 0; k < 4; k++)
#pragma unroll
            for (int j = 0; j < 5; j++) acc[k][j] = 0ull;

#pragma unroll
        for (int u = 0; u < 16; u++) {
            const ull w2 = Wq[hl + u];
            const ull aP = a2[2 * u], aQ = a2[2 * u + 1];
            float f0, f1, f2, f3;
            unpack2_(aP, f0, f1);
            unpack2_(aQ, f2, f3);
            const float s0 = rcpf(1.f + ex2f(f0));
            const float s1 = rcpf(1.f + ex2f(f1));
            const float s2 = rcpf(1.f + ex2f(f2));
            const float s3 = rcpf(1.f + ex2f(f3));
            a2[2 * u]     = fma2_(xP, w2, aP);
            a2[2 * u + 1] = fma2_(xQ, w2, aQ);
            const ull sA = pack2_(s0, s0);
            const ull sB = pack2_(s1, s1);
            const ull sC = pack2_(s2, s2);
            const ull sD = pack2_(s3, s3);
            const float* vr = Vp + (hl + u) * T_;
#pragma unroll
            for (int j = 0; j < 5; j++) {
                const ull vv = *(const ull*)(vr + 2 * j);
                acc[0][j] = fma2_(sA, vv, acc[0][j]);
                acc[1][j] = fma2_(sB, vv, acc[1][j]);
                acc[2][j] = fma2_(sC, vv, acc[2][j]);
                acc[3][j] = fma2_(sD, vv, acc[3][j]);
            }
        }

        // publish partials: RED[w][j][128 c] (c = L + 32k), ull = (t2j, t2j+1)
        {
            float* red = sm + SM_RED + (s & 1) * 10240;
#pragma unroll
            for (int k = 0; k < 4; k++)
#pragma unroll
                for (int j = 0; j < 5; j++)
                    *(ull*)(red + (w * 640 + j * 128 + k * 32 + L) * 2) = acc[k][j];
        }
    }

    // epilogue: reduce last step
    __syncthreads();
    if (w == ((len - 1) & 7)) {
        const float* red = sm + SM_RED + ((len - 1) & 1) * 10240;
        ull* gp = g_part + (((size_t)(i0 + len - 1) * 2 + tile) * 8 + qh) * 640;
#pragma unroll
        for (int j = 0; j < 5; j++)
#pragma unroll
            for (int p = 0; p < 4; p++) {
                const int c = p * 32 + L;
                ull v = *(const ull*)(red + (0 * 640 + j * 128 + c) * 2);
#pragma unroll
                for (int ww = 1; ww < 8; ww++)
                    v = add2_(v, *(const ull*)(red + (ww * 640 + j * 128 + c) * 2));
                gp[j * 128 + c] = v;
            }
    }
}

// ---------------- K5: combine 8 qh + bias + softmax, 8 d per block ----------------
__global__ __launch_bounds__(128) void k_softmax(const float* __restrict__ bias,
                                                 float* __restrict__ out) {
    __shared__ float buf[128 * T_ * 8];   // [b][t][dd] = 40KB
    const int d0   = blockIdx.x * 8;      // 98 blocks
    const int tile = blockIdx.y;          // 0..1
    const int b    = threadIdx.x;         // 0..127
    for (int dd = 0; dd < 8; dd++) {
        const int d = d0 + dd;
        const ull* gp = g_part + (((size_t)d * 2 + tile) * 8) * 640;
        ull v[5];
#pragma unroll
        for (int j = 0; j < 5; j++) v[j] = gp[j * 128 + b];
#pragma unroll
        for (int q = 1; q < 8; q++)
#pragma unroll
            for (int j = 0; j < 5; j++)
                v[j] = add2_(v[j], gp[q * 640 + j * 128 + b]);
        float l[T_];
#pragma unroll
        for (int j = 0; j < 5; j++) {
            unpack2_(v[j], l[2 * j], l[2 * j + 1]);
            l[2 * j]     += __ldg(bias + d * T_ + 2 * j);
            l[2 * j + 1] += __ldg(bias + d * T_ + 2 * j + 1);
        }
        float mx = l[0];
#pragma unroll
        for (int t = 1; t < T_; t++) mx = fmaxf(mx, l[t]);
        float e[T_]; float sum = 0.f;
#pragma unroll
        for (int t = 0; t < T_; t++) {
            e[t] = ex2f((l[t] - mx) * 1.4426950408889634f);
            sum += e[t];
        }
        const float r = rcpf(sum);
#pragma unroll
        for (int t = 0; t < T_; t++)
            buf[(b * T_ + t) * 8 + dd] = e[t] * r;
    }
    __syncthreads();
    // flush: float4 over dd
    const float4* bv = (const float4*)buf;
    for (int q = threadIdx.x; q < 128 * T_ * 2; q += 128) {
        const int bp   = q / 20;
        const int rr   = q - bp * 20;
        const int tt   = rr >> 1;
        const int half = rr & 1;
        *(float4*)(out + (size_t)(tile * 128 + bp) * (T_ * D_) + tt * D_ + d0 + half * 4) = bv[q];
    }
}

// ---------------- launch ----------------
extern "C" void kernel_launch(void* const* d_in, const int* in_sizes, int n_in,
                              void* d_out, int out_size) {
    const int*   x    = (const int*)d_in[0];
    const float* W    = (const float*)d_in[1];
    const float* c    = (const float*)d_in[2];
    const float* V    = (const float*)d_in[3];
    const float* bias = (const float*)d_in[4];
    float* out = (float*)d_out;

    static_assert(2 * SM_FLOATS * 4 <= 232448, "smem budget");
    cudaFuncSetAttribute(k_main, cudaFuncAttributeMaxDynamicSharedMemorySize,
                         SM_FLOATS * (int)sizeof(float));

    k_transW<<<dim3((D_ + 31) / 32, H_ / 32), dim3(32, 8)>>>(W);     // launch 1
    k_chunksum<<<dim3(32, NCH, 2), 512>>>(x);                        // launch 2
    k_prefix<<<(B_ * H_ / 2) / 256, 256>>>(c, x);                    // launch 3
    k_main<<<dim3(2, NCH, 8), 256, SM_FLOATS * (int)sizeof(float)>>>(V);  // launch 4 -> profiled
    k_softmax<<<dim3(D_ / 8, 2), 128>>>(bias, out);                  // launch 5
}

// round 15
// speedup vs baseline: 1.2330x; 1.1365x over previous
#include <cuda_runtime.h>
#include <cstdint>

#define B_   256
#define D_   784
#define H_   1024
#define T_   10
#define NCH  18
#define CHLEN 44

#define KNEG (-1.4426950408889634f)   // -log2(e)

typedef unsigned long long ull;

// ---------------- scratch ----------------
__device__ __align__(16) float  g_Wt[D_ * H_];          // (-log2e)*W^T [D][H] scalar (chunksum)
__device__ __align__(16) float2 g_Wt2[D_ * H_];         // duplicated (w,w) pairs (k_main)
__device__ __align__(16) float  g_Apre[NCH * B_ * H_];  // scaled chunk-start accumulators
__device__ __align__(16) ull    g_part[D_ * 4 * 4 * 320]; // partial logits [d][tile4][qh4][j5*64c]

// ---------------- helpers ----------------
__device__ __forceinline__ float ex2f(float x) {
    float y; asm("ex2.approx.f32 %0, %1;" : "=f"(y) : "f"(x)); return y;
}
__device__ __forceinline__ float rcpf(float x) {
    float y; asm("rcp.approx.f32 %0, %1;" : "=f"(y) : "f"(x)); return y;
}
__device__ __forceinline__ ull fma2_(ull a, ull b, ull c) {
    ull d; asm("fma.rn.f32x2 %0, %1, %2, %3;" : "=l"(d) : "l"(a), "l"(b), "l"(c)); return d;
}
__device__ __forceinline__ ull add2_(ull a, ull b) {
    ull d; asm("add.rn.f32x2 %0, %1, %2;" : "=l"(d) : "l"(a), "l"(b)); return d;
}
__device__ __forceinline__ ull pack2_(float lo, float hi) {
    ull d; asm("mov.b64 %0, {%1, %2};" : "=l"(d) : "f"(lo), "f"(hi)); return d;
}
__device__ __forceinline__ void unpack2_(ull v, float& lo, float& hi) {
    asm("mov.b64 {%0, %1}, %2;" : "=f"(lo), "=f"(hi) : "l"(v));
}
__device__ __forceinline__ void cp_async16(float* s, const float* g) {
    unsigned sa = (unsigned)__cvta_generic_to_shared(s);
    asm volatile("cp.async.ca.shared.global [%0], [%1], 16;\n" :: "r"(sa), "l"(g));
}
__device__ __forceinline__ void cp_commit() {
    asm volatile("cp.async.commit_group;\n" ::: "memory");
}

// ---------------- K1: transpose W -> scalar + duplicated ----------------
__global__ void k_transW(const float* __restrict__ W) {
    __shared__ float tile[32][33];
    int d = blockIdx.x * 32 + threadIdx.x;
    int h = blockIdx.y * 32 + threadIdx.y;
#pragma unroll
    for (int j = 0; j < 32; j += 8)
        if (d < D_) tile[threadIdx.y + j][threadIdx.x] = W[(h + j) * D_ + d] * KNEG;
    __syncthreads();
    int ho = blockIdx.y * 32 + threadIdx.x;
    int do_ = blockIdx.x * 32 + threadIdx.y;
#pragma unroll
    for (int j = 0; j < 32; j += 8)
        if (do_ + j < D_) {
            float v = tile[threadIdx.x][threadIdx.y + j];
            g_Wt [(do_ + j) * H_ + ho] = v;
            g_Wt2[(do_ + j) * H_ + ho] = make_float2(v, v);
        }
}

// ---------------- K2: chunk sums ----------------
__global__ __launch_bounds__(512) void k_chunksum(const int* __restrict__ x) {
    int bg = blockIdx.x;        // 0..31 (8 batches each)
    int k  = blockIdx.y;
    int i0 = k * CHLEN;
    int len = min(CHLEN, D_ - i0);
    __shared__ float xs2[CHLEN * 8];
    int tid = threadIdx.x;
    for (int idx = tid; idx < len * 8; idx += 512) {
        int j = idx >> 3, b = idx & 7;
        xs2[idx] = (float)x[(size_t)(bg * 8 + b) * D_ + i0 + j];
    }
    __syncthreads();
    int h0 = blockIdx.z * 512 + tid;
    float acc[8];
#pragma unroll
    for (int b = 0; b < 8; b++) acc[b] = 0.f;
    float wn1 = g_Wt[i0 * H_ + h0];
    float wn2 = (len > 1) ? g_Wt[(i0 + 1) * H_ + h0] : 0.f;
    for (int j = 0; j < len; j++) {
        float wv = wn1;
        wn1 = wn2;
        if (j + 2 < len) wn2 = g_Wt[(i0 + j + 2) * H_ + h0];
        const float* xr = &xs2[j * 8];
#pragma unroll
        for (int b = 0; b < 8; b++)
            acc[b] = fmaf(xr[b], wv, acc[b]);
    }
#pragma unroll
    for (int b = 0; b < 8; b++)
        g_Apre[(size_t)(k * B_ + bg * 8 + b) * H_ + h0] = acc[b];
}

// ---------------- K3: exclusive prefix (MLP=18) ----------------
__global__ void k_prefix(const float* __restrict__ c) {
    int idx = blockIdx.x * 256 + threadIdx.x;
    int b  = idx >> 9;
    int h0 = (idx & 511) * 2;
    float2 v[NCH];
#pragma unroll
    for (int k = 0; k < NCH; k++)
        v[k] = *(const float2*)&g_Apre[(size_t)(k * B_ + b) * H_ + h0];
    float2 acc = *(const float2*)&c[h0];
    acc.x *= KNEG; acc.y *= KNEG;
#pragma unroll
    for (int k = 0; k < NCH; k++) {
        *(float2*)&g_Apre[(size_t)(k * B_ + b) * H_ + h0] = acc;
        acc.x += v[k].x; acc.y += v[k].y;
    }
}

// ---------------- K4: main kernel (64 batches x 256 h per block) ----------------
// smem (floats): V 3*2560 ; Wdup 3*512 ; RED 2*5120
#define SM_V   0
#define SM_W   7680
#define SM_RED 9216
#define SM_FLOATS 19456     // 77824 B/block; x2 = 155648 <= 232448

__device__ __forceinline__ void stage(float* sm, int i, int srel, int hbase, int tid,
                                      const float* __restrict__ V) {
    const int bb = srel % 3;
    const float* vg = V + (size_t)i * (T_ * H_) + (size_t)hbase * T_;   // 2560 floats
    float* vs = sm + SM_V + bb * 2560;
    cp_async16(vs + tid * 4, vg + tid * 4);                     // [0,1024)
    cp_async16(vs + 1024 + tid * 4, vg + 1024 + tid * 4);       // [1024,2048)
    if (tid < 128)
        cp_async16(vs + 2048 + tid * 4, vg + 2048 + tid * 4);   // [2048,2560)
    else
        cp_async16(sm + SM_W + bb * 512 + (tid - 128) * 4,
                   ((const float*)(g_Wt2 + (size_t)i * H_ + hbase)) + (tid - 128) * 4);
}

__device__ __forceinline__ void step_compute(float* sm, ull* a2, ull x2,
                                             int hl, int w, int L, int srel) {
    const float* Vp = sm + SM_V + (srel % 3) * 2560;
    const ulonglong2* Wq = (const ulonglong2*)(sm + SM_W + (srel % 3) * 512);

    ull accA[5], accB[5];
#pragma unroll
    for (int j = 0; j < 5; j++) { accA[j] = 0ull; accB[j] = 0ull; }

#pragma unroll
    for (int p = 0; p < 16; p++) {      // h-pair (he, he+1), he = hl + 2p (even)
        const int he = hl + 2 * p;
        const ull aE = a2[2 * p], aO = a2[2 * p + 1];
        float fE0, fE1, fO0, fO1;
        unpack2_(aE, fE0, fE1);
        unpack2_(aO, fO0, fO1);
        const float sE0 = rcpf(1.f + ex2f(fE0));
        const float sE1 = rcpf(1.f + ex2f(fE1));
        const float sO0 = rcpf(1.f + ex2f(fO0));
        const float sO1 = rcpf(1.f + ex2f(fO1));

        const ulonglong2 wp = Wq[(hl >> 1) + p];     // ((we,we),(wo,wo))
        a2[2 * p]     = fma2_(x2, wp.x, aE);
        a2[2 * p + 1] = fma2_(x2, wp.y, aO);

        const ulonglong2* vc = (const ulonglong2*)(Vp + he * T_);  // 80B, 16B aligned
        const ulonglong2 c0 = vc[0];   // t01_e, t23_e
        const ulonglong2 c1 = vc[1];   // t45_e, t67_e
        const ulonglong2 c2 = vc[2];   // t89_e, t01_o
        const ulonglong2 c3 = vc[3];   // t23_o, t45_o
        const ulonglong2 c4 = vc[4];   // t67_o, t89_o

        const ull SE0 = pack2_(sE0, sE0);
        const ull SO0 = pack2_(sO0, sO0);
        accA[0] = fma2_(SE0, c0.x, accA[0]);
        accA[1] = fma2_(SE0, c0.y, accA[1]);
        accA[2] = fma2_(SE0, c1.x, accA[2]);
        accA[3] = fma2_(SE0, c1.y, accA[3]);
        accA[4] = fma2_(SE0, c2.x, accA[4]);
        accA[0] = fma2_(SO0, c2.y, accA[0]);
        accA[1] = fma2_(SO0, c3.x, accA[1]);
        accA[2] = fma2_(SO0, c3.y, accA[2]);
        accA[3] = fma2_(SO0, c4.x, accA[3]);
        accA[4] = fma2_(SO0, c4.y, accA[4]);

        const ull SE1 = pack2_(sE1, sE1);
        const ull SO1 = pack2_(sO1, sO1);
        accB[0] = fma2_(SE1, c0.x, accB[0]);
        accB[1] = fma2_(SE1, c0.y, accB[1]);
        accB[2] = fma2_(SE1, c1.x, accB[2]);
        accB[3] = fma2_(SE1, c1.y, accB[3]);
        accB[4] = fma2_(SE1, c2.x, accB[4]);
        accB[0] = fma2_(SO1, c2.y, accB[0]);
        accB[1] = fma2_(SO1, c3.x, accB[1]);
        accB[2] = fma2_(SO1, c3.y, accB[2]);
        accB[3] = fma2_(SO1, c4.x, accB[3]);
        accB[4] = fma2_(SO1, c4.y, accB[4]);
    }

    float* red = sm + SM_RED + (srel & 1) * 5120;
#pragma unroll
    for (int j = 0; j < 5; j++) {
        *(ull*)(red + ((w * 5 + j) * 64 + L) * 2)      = accA[j];
        *(ull*)(red + ((w * 5 + j) * 64 + 32 + L) * 2) = accB[j];
    }
}

__device__ __forceinline__ void reduce_store(const float* sm, ull* gp, int sdone, int L) {
    const float* red = sm + SM_RED + (sdone & 1) * 5120;
#pragma unroll
    for (int j = 0; j < 5; j++)
#pragma unroll
        for (int p = 0; p < 2; p++) {
            const int col = p * 32 + L;
            ull s = *(const ull*)(red + ((0 * 5 + j) * 64 + col) * 2);
#pragma unroll
            for (int ww = 1; ww < 8; ww++)
                s = add2_(s, *(const ull*)(red + ((ww * 5 + j) * 64 + col) * 2));
            gp[j * 64 + col] = s;
        }
}

__global__ __launch_bounds__(256, 2) void k_main(const int* __restrict__ xi,
                                                 const float* __restrict__ V) {
    extern __shared__ float sm[];
    const int tid   = threadIdx.x;
    const int w     = tid >> 5;       // 0..7
    const int L     = tid & 31;
    const int tile  = blockIdx.x;     // 0..3  (64 batches)
    const int chunk = blockIdx.y;     // 0..NCH-1
    const int qh    = blockIdx.z;     // 0..3  (256 h)
    const int i0  = chunk * CHLEN;
    const int len = min(CHLEN, D_ - i0);
    const int hbase = qh * 256;
    const int hl  = w * 32;           // local h within quarter
    const int h0  = hbase + hl;

    // a2[u] = (A[b0][h0+u], A[b1][h0+u]); b0 = tile*64+L, b1 = b0+32
    ull a2[32];
    {
        const float* ap0 = g_Apre + ((size_t)(chunk * B_ + tile * 64 + L)) * H_ + h0;
        const float* ap1 = ap0 + (size_t)32 * H_;
#pragma unroll
        for (int g = 0; g < 8; g++) {
            float4 va = *(const float4*)(ap0 + 4 * g);
            float4 vb = *(const float4*)(ap1 + 4 * g);
            a2[4 * g + 0] = pack2_(va.x, vb.x);
            a2[4 * g + 1] = pack2_(va.y, vb.y);
            a2[4 * g + 2] = pack2_(va.z, vb.z);
            a2[4 * g + 3] = pack2_(va.w, vb.w);
        }
    }

    stage(sm, i0, 0, hbase, tid, V); cp_commit();
    if (len > 1) { stage(sm, i0 + 1, 1, hbase, tid, V); cp_commit(); }

    const int* xrow0 = xi + (size_t)(tile * 64 + L) * D_ + i0;
    const int* xrow1 = xrow0 + (size_t)32 * D_;
    float x0buf[2], x1buf[2];
    x0buf[0] = (float)__ldg(xrow0);     x1buf[0] = (float)__ldg(xrow1);
    x0buf[1] = (len > 1) ? (float)__ldg(xrow0 + 1) : 0.f;
    x1buf[1] = (len > 1) ? (float)__ldg(xrow1 + 1) : 0.f;

    for (int s = 0; s < len; s++) {
        if (s + 1 < len) asm volatile("cp.async.wait_group 1;\n" ::: "memory");
        else             asm volatile("cp.async.wait_group 0;\n" ::: "memory");
        __syncthreads();

        const ull x2 = pack2_(x0buf[s & 1], x1buf[s & 1]);
        if (s + 2 < len) {
            x0buf[s & 1] = (float)__ldg(xrow0 + s + 2);
            x1buf[s & 1] = (float)__ldg(xrow1 + s + 2);
            stage(sm, i0 + s + 2, s + 2, hbase, tid, V); cp_commit();
        }

        if (s >= 1 && w == ((s - 1) & 7)) {
            ull* gp = g_part + ((size_t)((i0 + s - 1) * 4 + tile) * 4 + qh) * 320;
            reduce_store(sm, gp, s - 1, L);
        }

        step_compute(sm, a2, x2, hl, w, L, s);
    }

    __syncthreads();
    if (w == ((len - 1) & 7)) {
        ull* gp = g_part + ((size_t)((i0 + len - 1) * 4 + tile) * 4 + qh) * 320;
        reduce_store(sm, gp, len - 1, L);
    }
}

// ---------------- K5: combine quarters + bias + softmax, 8 d per block ----------------
__global__ __launch_bounds__(64) void k_softmax(const float* __restrict__ bias,
                                                float* __restrict__ out) {
    __shared__ float buf[64 * T_ * 8];    // [b][t][dd] = 20KB
    const int d0   = blockIdx.x * 8;      // 98 blocks
    const int tile = blockIdx.y;          // 0..3
    const int b    = threadIdx.x;         // 0..63
    for (int dd = 0; dd < 8; dd++) {
        const int d = d0 + dd;
        const ull* gp = g_part + ((size_t)(d * 4 + tile) * 4) * 320;
        ull v[5];
#pragma unroll
        for (int j = 0; j < 5; j++) v[j] = gp[j * 64 + b];
#pragma unroll
        for (int q = 1; q < 4; q++)
#pragma unroll
            for (int j = 0; j < 5; j++)
                v[j] = add2_(v[j], gp[q * 320 + j * 64 + b]);
        float l[T_];
#pragma unroll
        for (int j = 0; j < 5; j++) {
            unpack2_(v[j], l[2 * j], l[2 * j + 1]);
            l[2 * j]     += __ldg(bias + d * T_ + 2 * j);
            l[2 * j + 1] += __ldg(bias + d * T_ + 2 * j + 1);
        }
        float mx = l[0];
#pragma unroll
        for (int t = 1; t < T_; t++) mx = fmaxf(mx, l[t]);
        float e[T_]; float sum = 0.f;
#pragma unroll
        for (int t = 0; t < T_; t++) {
            e[t] = ex2f((l[t] - mx) * 1.4426950408889634f);
            sum += e[t];
        }
        const float r = rcpf(sum);
#pragma unroll
        for (int t = 0; t < T_; t++)
            buf[(b * T_ + t) * 8 + dd] = e[t] * r;
    }
    __syncthreads();
    // flush as float4 over dd
    const float4* bv = (const float4*)buf;
    for (int q = threadIdx.x; q < 64 * T_ * 2; q += 64) {
        const int bp   = q / 20;
        const int rr   = q - bp * 20;
        const int tt   = rr >> 1;
        const int half = rr & 1;
        *(float4*)(out + (size_t)(tile * 64 + bp) * (T_ * D_) + tt * D_ + d0 + half * 4) = bv[q];
    }
}

// ---------------- launch ----------------
extern "C" void kernel_launch(void* const* d_in, const int* in_sizes, int n_in,
                              void* d_out, int out_size) {
    const int*   x    = (const int*)d_in[0];
    const float* W    = (const float*)d_in[1];
    const float* c    = (const float*)d_in[2];
    const float* V    = (const float*)d_in[3];
    const float* bias = (const float*)d_in[4];
    float* out = (float*)d_out;

    static_assert(2 * SM_FLOATS * 4 <= 232448, "smem budget");
    cudaFuncSetAttribute(k_main, cudaFuncAttributeMaxDynamicSharedMemorySize,
                         SM_FLOATS * (int)sizeof(float));

    k_transW<<<dim3((D_ + 31) / 32, H_ / 32), dim3(32, 8)>>>(W);     // launch 1
    k_chunksum<<<dim3(32, NCH, 2), 512>>>(x);                        // launch 2
    k_prefix<<<(B_ * H_ / 2) / 256, 256>>>(c);                       // launch 3
    k_main<<<dim3(4, NCH, 4), 256, SM_FLOATS * (int)sizeof(float)>>>(x, V);  // launch 4 -> profiled
    k_softmax<<<dim3(D_ / 8, 4), 64>>>(bias, out);                   // launch 5
}